// round 7
// baseline (speedup 1.0000x reference)
#include <cuda_runtime.h>
#include <cuda_bf16.h>
#include <cstdint>
#include <math.h>

#define S_LEN  1024
#define BATCH  8
#define DMODEL 256
#define NH     8
#define HDIM   32
#define DFF    1024
#define MROWS  (S_LEN * BATCH)   // 8192
#define LN_EPS 1e-5f

// ---------------- scratch: packed bf16x2 hi/lo pair arrays -----------------
#define NPAIR_D   (MROWS * DMODEL / 2)   // 1M pairs
#define NPAIR_FF  (MROWS * DFF / 2)      // 4M pairs
__device__ uint32_t g_xh [NPAIR_D], g_xl [NPAIR_D];    // LN1 out
__device__ uint32_t g_qh [NPAIR_D], g_ql [NPAIR_D];    // [bh][t][d-pair]
__device__ uint32_t g_kh [NPAIR_D], g_kl [NPAIR_D];    // [bh][t][d-pair]
__device__ uint32_t g_vth[NPAIR_D], g_vtl[NPAIR_D];    // [bh][d][t-pair] (transposed!)
__device__ uint32_t g_ch [NPAIR_D], g_cl [NPAIR_D];    // attention ctx
__device__ uint32_t g_x2h[NPAIR_D], g_x2l[NPAIR_D];    // x + attn_out
__device__ uint32_t g_yh [NPAIR_D], g_yl [NPAIR_D];    // LN2 out
__device__ uint32_t g_f1h[NPAIR_FF], g_f1l[NPAIR_FF];  // relu(ff1)
// pre-split weights
__device__ uint32_t g_wih[3 * DMODEL * DMODEL / 2], g_wil[3 * DMODEL * DMODEL / 2];
__device__ uint32_t g_woh[DMODEL * DMODEL / 2],     g_wol[DMODEL * DMODEL / 2];
__device__ uint32_t g_w1h[DFF * DMODEL / 2],        g_w1l[DFF * DMODEL / 2];
__device__ uint32_t g_w2h[DMODEL * DFF / 2],        g_w2l[DMODEL * DFF / 2];

// ---------------- helpers --------------------------------------------------
__device__ __forceinline__ void mma16816(float* c, const uint32_t* a, uint32_t b0, uint32_t b1) {
    asm volatile(
        "mma.sync.aligned.m16n8k16.row.col.f32.bf16.bf16.f32 "
        "{%0,%1,%2,%3}, {%4,%5,%6,%7}, {%8,%9}, {%0,%1,%2,%3};"
        : "+f"(c[0]), "+f"(c[1]), "+f"(c[2]), "+f"(c[3])
        : "r"(a[0]), "r"(a[1]), "r"(a[2]), "r"(a[3]), "r"(b0), "r"(b1));
}
__device__ __forceinline__ void split_bf16x2(float x, float y, uint32_t& hi, uint32_t& lo) {
    __nv_bfloat162 h = __floats2bfloat162_rn(x, y);
    float hx = __bfloat162float(h.x), hy = __bfloat162float(h.y);
    __nv_bfloat162 l = __floats2bfloat162_rn(x - hx, y - hy);
    hi = *reinterpret_cast<uint32_t*>(&h);
    lo = *reinterpret_cast<uint32_t*>(&l);
}
__device__ __forceinline__ float2 unsplit(uint32_t h, uint32_t l) {
    __nv_bfloat162 hh = *reinterpret_cast<__nv_bfloat162*>(&h);
    __nv_bfloat162 ll = *reinterpret_cast<__nv_bfloat162*>(&l);
    return make_float2(__bfloat162float(hh.x) + __bfloat162float(ll.x),
                       __bfloat162float(hh.y) + __bfloat162float(ll.y));
}

// ---------------- weight pre-split ----------------------------------------
__global__ void wsplit_kernel(const float* __restrict__ w,
                              uint32_t* __restrict__ wh, uint32_t* __restrict__ wl,
                              int npairs) {
    int i = blockIdx.x * 256 + threadIdx.x;
    if (i < npairs) {
        float2 v = ((const float2*)w)[i];
        uint32_t h, l;
        split_bf16x2(v.x, v.y, h, l);
        wh[i] = h; wl[i] = l;
    }
}

// ---------------- LayerNorm: warp per row, pair output ---------------------
template<bool INPAIR>
__global__ void ln_kernel(const float* __restrict__ in,
                          const uint32_t* __restrict__ inh, const uint32_t* __restrict__ inl,
                          const float* __restrict__ gw, const float* __restrict__ bw,
                          uint32_t* __restrict__ outh, uint32_t* __restrict__ outl) {
    int row  = blockIdx.x * blockDim.y + threadIdx.y;
    int lane = threadIdx.x;
    float4 v0, v1;
    if (INPAIR) {
        uint2 h0 = ((const uint2*)(inh + (size_t)row * 128))[lane];
        uint2 l0 = ((const uint2*)(inl + (size_t)row * 128))[lane];
        uint2 h1 = ((const uint2*)(inh + (size_t)row * 128 + 64))[lane];
        uint2 l1 = ((const uint2*)(inl + (size_t)row * 128 + 64))[lane];
        float2 a = unsplit(h0.x, l0.x), b = unsplit(h0.y, l0.y);
        v0 = make_float4(a.x, a.y, b.x, b.y);
        a = unsplit(h1.x, l1.x); b = unsplit(h1.y, l1.y);
        v1 = make_float4(a.x, a.y, b.x, b.y);
    } else {
        const float4* xp = (const float4*)(in + (size_t)row * DMODEL);
        v0 = xp[lane];
        v1 = xp[lane + 32];
    }
    float s = v0.x + v0.y + v0.z + v0.w + v1.x + v1.y + v1.z + v1.w;
#pragma unroll
    for (int o = 16; o > 0; o >>= 1) s += __shfl_xor_sync(0xffffffffu, s, o);
    float mu = s * (1.0f / DMODEL);
    float d0x = v0.x - mu, d0y = v0.y - mu, d0z = v0.z - mu, d0w = v0.w - mu;
    float d1x = v1.x - mu, d1y = v1.y - mu, d1z = v1.z - mu, d1w = v1.w - mu;
    float q = d0x*d0x + d0y*d0y + d0z*d0z + d0w*d0w
            + d1x*d1x + d1y*d1y + d1z*d1z + d1w*d1w;
#pragma unroll
    for (int o = 16; o > 0; o >>= 1) q += __shfl_xor_sync(0xffffffffu, q, o);
    float rs = rsqrtf(q * (1.0f / DMODEL) + LN_EPS);
    const float4* gp = (const float4*)gw;
    const float4* bp = (const float4*)bw;
    float4 ga = gp[lane], gb = gp[lane + 32];
    float4 ba = bp[lane], bb = bp[lane + 32];
    float o0x = d0x * rs * ga.x + ba.x, o0y = d0y * rs * ga.y + ba.y;
    float o0z = d0z * rs * ga.z + ba.z, o0w = d0w * rs * ga.w + ba.w;
    float o1x = d1x * rs * gb.x + bb.x, o1y = d1y * rs * gb.y + bb.y;
    float o1z = d1z * rs * gb.z + bb.z, o1w = d1w * rs * gb.w + bb.w;
    uint2 ph, pl;
    split_bf16x2(o0x, o0y, ph.x, pl.x);
    split_bf16x2(o0z, o0w, ph.y, pl.y);
    ((uint2*)(outh + (size_t)row * 128))[lane] = ph;
    ((uint2*)(outl + (size_t)row * 128))[lane] = pl;
    split_bf16x2(o1x, o1y, ph.x, pl.x);
    split_bf16x2(o1z, o1w, ph.y, pl.y);
    ((uint2*)(outh + (size_t)row * 128 + 64))[lane] = ph;
    ((uint2*)(outl + (size_t)row * 128 + 64))[lane] = pl;
}

// ================= pair-input bf16-split tensor GEMM =======================
// C[M,N] = A @ W^T. A/W pre-split pair arrays. Block 128 x BN, BK=32(=16 pairs),
// 256 threads = 8 warps (4m x 2n), warp tile 32 x BN/2.
// MODE: 1 = bias+relu -> pair, 2 = bias+resid -> pair, 4 = bias+resid -> fp32,
//       3 = qkv scatter (q scaled; k standard pairs; v transposed t-pairs)
#define GP 20   // smem row pitch in uint32 (16 used)
template<int MODE, int BN>
__global__ void __launch_bounds__(256) gemm_pair_kernel(
    const uint32_t* __restrict__ Ah, const uint32_t* __restrict__ Al,
    const uint32_t* __restrict__ Wh, const uint32_t* __restrict__ Wl,
    const float* __restrict__ bias,
    const uint32_t* __restrict__ Rh, const uint32_t* __restrict__ Rl,
    uint32_t* __restrict__ Ch, uint32_t* __restrict__ Cl,
    float* __restrict__ Cf,
    uint32_t* __restrict__ qh_o, uint32_t* __restrict__ ql_o,
    uint32_t* __restrict__ kh_o, uint32_t* __restrict__ kl_o,
    uint32_t* __restrict__ vth_o, uint32_t* __restrict__ vtl_o,
    int K, int N)
{
    constexpr int NT = BN / 16;               // n-tiles per warp
    __shared__ uint32_t sAh[128 * GP], sAl[128 * GP];
    __shared__ uint32_t sWh[BN * GP],  sWl[BN * GP];

    int tid = threadIdx.x;
    int warp = tid >> 5, lane = tid & 31;
    int g = lane >> 2, q4 = lane & 3;
    int wm = warp >> 1, wn = warp & 1;
    int m0 = wm * 32, n0 = wn * (BN / 2);
    int rowBase = blockIdx.y * 128;
    int colBase = blockIdx.x * BN;
    int Kp = K >> 1;

    // A staging: 2 threads/row, 8 uint32 each
    int lrA = tid >> 1, lcA = (tid & 1) * 8;
    const uint32_t* ApH = Ah + (size_t)(rowBase + lrA) * Kp + lcA;
    const uint32_t* ApL = Al + (size_t)(rowBase + lrA) * Kp + lcA;
    // W staging
    int lrW, lcW;
    if (BN == 128) { lrW = tid >> 1; lcW = (tid & 1) * 8; }
    else           { lrW = tid >> 2; lcW = (tid & 3) * 4; }
    const uint32_t* WpH = Wh + (size_t)(colBase + lrW) * Kp + lcW;
    const uint32_t* WpL = Wl + (size_t)(colBase + lrW) * Kp + lcW;

    float c[2][NT][4];
#pragma unroll
    for (int mt = 0; mt < 2; mt++)
#pragma unroll
        for (int nt = 0; nt < NT; nt++)
#pragma unroll
            for (int i = 0; i < 4; i++) c[mt][nt][i] = 0.0f;

    for (int kp = 0; kp < Kp; kp += 16) {
        *(uint4*)(sAh + lrA * GP + lcA)     = *(const uint4*)(ApH + kp);
        *(uint4*)(sAh + lrA * GP + lcA + 4) = *(const uint4*)(ApH + kp + 4);
        *(uint4*)(sAl + lrA * GP + lcA)     = *(const uint4*)(ApL + kp);
        *(uint4*)(sAl + lrA * GP + lcA + 4) = *(const uint4*)(ApL + kp + 4);
        if (BN == 128) {
            *(uint4*)(sWh + lrW * GP + lcW)     = *(const uint4*)(WpH + kp);
            *(uint4*)(sWh + lrW * GP + lcW + 4) = *(const uint4*)(WpH + kp + 4);
            *(uint4*)(sWl + lrW * GP + lcW)     = *(const uint4*)(WpL + kp);
            *(uint4*)(sWl + lrW * GP + lcW + 4) = *(const uint4*)(WpL + kp + 4);
        } else {
            *(uint4*)(sWh + lrW * GP + lcW) = *(const uint4*)(WpH + kp);
            *(uint4*)(sWl + lrW * GP + lcW) = *(const uint4*)(WpL + kp);
        }
        __syncthreads();

#pragma unroll
        for (int ks = 0; ks < 2; ks++) {
            int kb = ks * 8;
            uint32_t ah[2][4], al[2][4];
#pragma unroll
            for (int mt = 0; mt < 2; mt++) {
                int r0 = (m0 + mt * 16 + g) * GP + kb + q4;
                int r1 = (m0 + mt * 16 + g + 8) * GP + kb + q4;
                ah[mt][0] = sAh[r0];     ah[mt][1] = sAh[r1];
                ah[mt][2] = sAh[r0 + 4]; ah[mt][3] = sAh[r1 + 4];
                al[mt][0] = sAl[r0];     al[mt][1] = sAl[r1];
                al[mt][2] = sAl[r0 + 4]; al[mt][3] = sAl[r1 + 4];
            }
#pragma unroll
            for (int nt = 0; nt < NT; nt++) {
                int rb = (n0 + nt * 8 + g) * GP + kb + q4;
                uint32_t bh0 = sWh[rb], bh1 = sWh[rb + 4];
                uint32_t bl0 = sWl[rb], bl1 = sWl[rb + 4];
#pragma unroll
                for (int mt = 0; mt < 2; mt++) {
                    mma16816(c[mt][nt], ah[mt], bh0, bh1);
                    mma16816(c[mt][nt], ah[mt], bl0, bl1);
                    mma16816(c[mt][nt], al[mt], bh0, bh1);
                }
            }
        }
        __syncthreads();
    }

    // ---- epilogue ----
    int Np = N >> 1;
#pragma unroll
    for (int mt = 0; mt < 2; mt++) {
        int r0 = rowBase + m0 + mt * 16 + g;      // half0 row (r0+8 = half1)
#pragma unroll
        for (int nt = 0; nt < NT; nt++) {
            int cc = colBase + n0 + nt * 8 + 2 * q4;
            float bv0 = bias[cc], bv1 = bias[cc + 1];
            float v00 = c[mt][nt][0] + bv0, v01 = c[mt][nt][1] + bv1;
            float v10 = c[mt][nt][2] + bv0, v11 = c[mt][nt][3] + bv1;
            if (MODE == 1) {
                v00 = fmaxf(v00, 0.0f); v01 = fmaxf(v01, 0.0f);
                v10 = fmaxf(v10, 0.0f); v11 = fmaxf(v11, 0.0f);
            }
            if (MODE == 2 || MODE == 4) {
                size_t i0 = (size_t)r0 * Np + (cc >> 1);
                size_t i1 = (size_t)(r0 + 8) * Np + (cc >> 1);
                float2 ra = unsplit(Rh[i0], Rl[i0]);
                float2 rb2 = unsplit(Rh[i1], Rl[i1]);
                v00 += ra.x; v01 += ra.y; v10 += rb2.x; v11 += rb2.y;
            }
            if (MODE == 1 || MODE == 2) {
                uint32_t h, l;
                size_t i0 = (size_t)r0 * Np + (cc >> 1);
                split_bf16x2(v00, v01, h, l); Ch[i0] = h; Cl[i0] = l;
                size_t i1 = (size_t)(r0 + 8) * Np + (cc >> 1);
                split_bf16x2(v10, v11, h, l); Ch[i1] = h; Cl[i1] = l;
            } else if (MODE == 4) {
                *(float2*)&Cf[(size_t)r0 * N + cc]       = make_float2(v00, v01);
                *(float2*)&Cf[(size_t)(r0 + 8) * N + cc] = make_float2(v10, v11);
            } else if (MODE == 3) {
                int s0 = r0 >> 3, b = r0 & 7;      // s0 even; half1 -> s0+1
                int part = cc >> 8;
                int h8 = (cc & 255) >> 5;
                int hd = cc & 31;
                int bh = b * NH + h8;
                uint32_t h, l;
                if (part == 0) {
                    const float sc = 0.17677669529663687f;  // 1/sqrt(32)
                    size_t i0 = ((size_t)bh * S_LEN + s0) * 16 + (hd >> 1);
                    split_bf16x2(v00 * sc, v01 * sc, h, l); qh_o[i0] = h; ql_o[i0] = l;
                    size_t i1 = i0 + 16;
                    split_bf16x2(v10 * sc, v11 * sc, h, l); qh_o[i1] = h; ql_o[i1] = l;
                } else if (part == 1) {
                    size_t i0 = ((size_t)bh * S_LEN + s0) * 16 + (hd >> 1);
                    split_bf16x2(v00, v01, h, l); kh_o[i0] = h; kl_o[i0] = l;
                    size_t i1 = i0 + 16;
                    split_bf16x2(v10, v11, h, l); kh_o[i1] = h; kl_o[i1] = l;
                } else {
                    // transposed: t-pair (s0, s0+1) for d = hd and hd+1
                    size_t i0 = ((size_t)bh * HDIM + hd) * (S_LEN / 2) + (s0 >> 1);
                    split_bf16x2(v00, v10, h, l); vth_o[i0] = h; vtl_o[i0] = l;
                    size_t i1 = i0 + (S_LEN / 2);
                    split_bf16x2(v01, v11, h, l); vth_o[i1] = h; vtl_o[i1] = l;
                }
            }
        }
    }
}

// ================= pair-input bf16-split flash attention ===================
// Block 256 = 8 warps, warp owns 16 q-rows; BM=128, chunk BN=64, HD=32.
// K/V/Q pre-split: staging is pure copy. P repacked in registers.
#define PK 20    // sK pitch (uint32; 16 used)
#define PV2 36   // sVt pitch (uint32; 32 used)

__global__ void __launch_bounds__(256) attn_pair_kernel(
    const uint32_t* __restrict__ qh_g, const uint32_t* __restrict__ ql_g,
    const uint32_t* __restrict__ kh_g, const uint32_t* __restrict__ kl_g,
    const uint32_t* __restrict__ vth_g, const uint32_t* __restrict__ vtl_g,
    const float* __restrict__ biasg,
    uint32_t* __restrict__ ctxh, uint32_t* __restrict__ ctxl)
{
    __shared__ uint32_t sKh[64 * PK], sKl[64 * PK];
    __shared__ uint32_t sVh[32 * PV2], sVl[32 * PV2];

    int tid  = threadIdx.x;
    int warp = tid >> 5, lane = tid & 31;
    int g = lane >> 2, q4 = lane & 3;
    int bh = blockIdx.y, qt = blockIdx.x;
    int b = bh >> 3, h = bh & 7;
    int rA = warp * 16 + g;
    int rB = rA + 8;

    const uint32_t* qbh = qh_g + ((size_t)bh * S_LEN + (size_t)qt * 128) * 16;
    const uint32_t* qbl = ql_g + ((size_t)bh * S_LEN + (size_t)qt * 128) * 16;
    const float* biasA = biasg + ((size_t)bh * S_LEN + (size_t)(qt * 128 + rA)) * S_LEN;
    const float* biasB = biasA + (size_t)8 * S_LEN;

    // ---- Q fragments: direct pair loads ----
    uint32_t qh[2][4], ql[2][4];
#pragma unroll
    for (int kt = 0; kt < 2; kt++) {
        int kp = kt * 8 + q4;
        qh[kt][0] = qbh[rA * 16 + kp];     ql[kt][0] = qbl[rA * 16 + kp];
        qh[kt][1] = qbh[rB * 16 + kp];     ql[kt][1] = qbl[rB * 16 + kp];
        qh[kt][2] = qbh[rA * 16 + kp + 4]; ql[kt][2] = qbl[rA * 16 + kp + 4];
        qh[kt][3] = qbh[rB * 16 + kp + 4]; ql[kt][3] = qbl[rB * 16 + kp + 4];
    }

    float mA = -1e30f, mB = -1e30f, lA = 0.0f, lB = 0.0f;
    float o[4][4];
#pragma unroll
    for (int nt = 0; nt < 4; nt++)
#pragma unroll
        for (int i = 0; i < 4; i++) o[nt][i] = 0.0f;

    // staging maps: K: t=tid>>2 (0..63), dp=(tid&3)*4 ; V: d=tid>>3 (0..31), tp=(tid&7)*4
    int tK = tid >> 2, dK = (tid & 3) * 4;
    int dV = tid >> 3, tV = (tid & 7) * 4;
    const uint32_t* kbh = kh_g + (size_t)bh * S_LEN * 16;
    const uint32_t* kbl = kl_g + (size_t)bh * S_LEN * 16;
    const uint32_t* vbh = vth_g + (size_t)bh * HDIM * (S_LEN / 2);
    const uint32_t* vbl = vtl_g + (size_t)bh * HDIM * (S_LEN / 2);

    for (int j = 0; j < 16; j++) {
        // ---- stage K [t][d-pair] and V^T [d][t-pair]: pure copies ----
        *(uint4*)(sKh + tK * PK + dK) = *(const uint4*)(kbh + (size_t)(j * 64 + tK) * 16 + dK);
        *(uint4*)(sKl + tK * PK + dK) = *(const uint4*)(kbl + (size_t)(j * 64 + tK) * 16 + dK);
        *(uint4*)(sVh + dV * PV2 + tV) = *(const uint4*)(vbh + (size_t)dV * (S_LEN / 2) + j * 32 + tV);
        *(uint4*)(sVl + dV * PV2 + tV) = *(const uint4*)(vbl + (size_t)dV * (S_LEN / 2) + j * 32 + tV);
        __syncthreads();

        // ---- C init with bias (read once from DRAM) ----
        float c[8][4];
#pragma unroll
        for (int nt = 0; nt < 8; nt++) {
            float2 bA = *(const float2*)(biasA + j * 64 + nt * 8 + 2 * q4);
            float2 bB = *(const float2*)(biasB + j * 64 + nt * 8 + 2 * q4);
            c[nt][0] = bA.x; c[nt][1] = bA.y; c[nt][2] = bB.x; c[nt][3] = bB.y;
        }

        // ---- QK^T: 8 n-tiles x 2 k16 x 3 split-MMAs ----
#pragma unroll
        for (int nt = 0; nt < 8; nt++) {
#pragma unroll
            for (int kt = 0; kt < 2; kt++) {
                int rb = (nt * 8 + g) * PK + kt * 8 + q4;
                uint32_t bh0 = sKh[rb], bh1 = sKh[rb + 4];
                uint32_t bl0 = sKl[rb], bl1 = sKl[rb + 4];
                mma16816(c[nt], qh[kt], bh0, bh1);
                mma16816(c[nt], qh[kt], bl0, bl1);
                mma16816(c[nt], ql[kt], bh0, bh1);
            }
        }

        // ---- online softmax ----
        float mxA = -1e30f, mxB = -1e30f;
#pragma unroll
        for (int nt = 0; nt < 8; nt++) {
            mxA = fmaxf(mxA, fmaxf(c[nt][0], c[nt][1]));
            mxB = fmaxf(mxB, fmaxf(c[nt][2], c[nt][3]));
        }
        mxA = fmaxf(mxA, __shfl_xor_sync(0xffffffffu, mxA, 1));
        mxA = fmaxf(mxA, __shfl_xor_sync(0xffffffffu, mxA, 2));
        mxB = fmaxf(mxB, __shfl_xor_sync(0xffffffffu, mxB, 1));
        mxB = fmaxf(mxB, __shfl_xor_sync(0xffffffffu, mxB, 2));
        float nmA = fmaxf(mA, mxA), nmB = fmaxf(mB, mxB);
        float corrA = __expf(mA - nmA), corrB = __expf(mB - nmB);
        mA = nmA; mB = nmB;
        float sA = 0.0f, sB = 0.0f;
#pragma unroll
        for (int nt = 0; nt < 8; nt++) {
            c[nt][0] = __expf(c[nt][0] - nmA);
            c[nt][1] = __expf(c[nt][1] - nmA);
            c[nt][2] = __expf(c[nt][2] - nmB);
            c[nt][3] = __expf(c[nt][3] - nmB);
            sA += c[nt][0] + c[nt][1];
            sB += c[nt][2] + c[nt][3];
        }
        sA += __shfl_xor_sync(0xffffffffu, sA, 1);
        sA += __shfl_xor_sync(0xffffffffu, sA, 2);
        sB += __shfl_xor_sync(0xffffffffu, sB, 1);
        sB += __shfl_xor_sync(0xffffffffu, sB, 2);
        lA = lA * corrA + sA;
        lB = lB * corrB + sB;
#pragma unroll
        for (int nt = 0; nt < 4; nt++) {
            o[nt][0] *= corrA; o[nt][1] *= corrA;
            o[nt][2] *= corrB; o[nt][3] *= corrB;
        }

        // ---- repack P (C-frag == PV A-frag layout), split hi/lo ----
        uint32_t ph[4][4], pl[4][4];
#pragma unroll
        for (int kk = 0; kk < 4; kk++) {
            split_bf16x2(c[2 * kk][0],     c[2 * kk][1],     ph[kk][0], pl[kk][0]);
            split_bf16x2(c[2 * kk][2],     c[2 * kk][3],     ph[kk][1], pl[kk][1]);
            split_bf16x2(c[2 * kk + 1][0], c[2 * kk + 1][1], ph[kk][2], pl[kk][2]);
            split_bf16x2(c[2 * kk + 1][2], c[2 * kk + 1][3], ph[kk][3], pl[kk][3]);
        }

        // ---- PV: 4 k16 x 4 n-tiles x 3 split-MMAs ----
#pragma unroll
        for (int kk = 0; kk < 4; kk++) {
#pragma unroll
            for (int nt = 0; nt < 4; nt++) {
                int rb = (nt * 8 + g) * PV2 + kk * 8 + q4;
                uint32_t bh0 = sVh[rb], bh1 = sVh[rb + 4];
                uint32_t bl0 = sVl[rb], bl1 = sVl[rb + 4];
                mma16816(o[nt], ph[kk], bh0, bh1);
                mma16816(o[nt], ph[kk], bl0, bl1);
                mma16816(o[nt], pl[kk], bh0, bh1);
            }
        }
        __syncthreads();
    }

    // ---- epilogue: normalize, split, write ctx pairs ----
    float invA = 1.0f / lA, invB = 1.0f / lB;
    size_t baseA = ((size_t)(qt * 128 + rA) * BATCH + b) * 128 + h * 16 + q4;
    size_t baseB = ((size_t)(qt * 128 + rB) * BATCH + b) * 128 + h * 16 + q4;
#pragma unroll
    for (int nt = 0; nt < 4; nt++) {
        uint32_t hh, ll;
        split_bf16x2(o[nt][0] * invA, o[nt][1] * invA, hh, ll);
        ctxh[baseA + nt * 4] = hh; ctxl[baseA + nt * 4] = ll;
        split_bf16x2(o[nt][2] * invB, o[nt][3] * invB, hh, ll);
        ctxh[baseB + nt * 4] = hh; ctxl[baseB + nt * 4] = ll;
    }
}

// ---------------- launch ---------------------------------------------------
extern "C" void kernel_launch(void* const* d_in, const int* in_sizes, int n_in,
                              void* d_out, int out_size) {
    const float* src   = (const float*)d_in[0];
    const float* bias  = (const float*)d_in[1];
    const float* in_w  = (const float*)d_in[2];
    const float* in_b  = (const float*)d_in[3];
    const float* out_w = (const float*)d_in[4];
    const float* out_b = (const float*)d_in[5];
    const float* w1    = (const float*)d_in[6];
    const float* b1    = (const float*)d_in[7];
    const float* w2    = (const float*)d_in[8];
    const float* b2    = (const float*)d_in[9];
    const float* g1    = (const float*)d_in[10];
    const float* be1   = (const float*)d_in[11];
    const float* g2    = (const float*)d_in[12];
    const float* be2   = (const float*)d_in[13];
    float* out = (float*)d_out;

    uint32_t *pxh, *pxl, *pqh, *pql, *pkh, *pkl, *pvth, *pvtl;
    uint32_t *pch, *pcl, *px2h, *px2l, *pyh, *pyl, *pf1h, *pf1l;
    uint32_t *pwih, *pwil, *pwoh, *pwol, *pw1h, *pw1l, *pw2h, *pw2l;
    cudaGetSymbolAddress((void**)&pxh,  g_xh);  cudaGetSymbolAddress((void**)&pxl,  g_xl);
    cudaGetSymbolAddress((void**)&pqh,  g_qh);  cudaGetSymbolAddress((void**)&pql,  g_ql);
    cudaGetSymbolAddress((void**)&pkh,  g_kh);  cudaGetSymbolAddress((void**)&pkl,  g_kl);
    cudaGetSymbolAddress((void**)&pvth, g_vth); cudaGetSymbolAddress((void**)&pvtl, g_vtl);
    cudaGetSymbolAddress((void**)&pch,  g_ch);  cudaGetSymbolAddress((void**)&pcl,  g_cl);
    cudaGetSymbolAddress((void**)&px2h, g_x2h); cudaGetSymbolAddress((void**)&px2l, g_x2l);
    cudaGetSymbolAddress((void**)&pyh,  g_yh);  cudaGetSymbolAddress((void**)&pyl,  g_yl);
    cudaGetSymbolAddress((void**)&pf1h, g_f1h); cudaGetSymbolAddress((void**)&pf1l, g_f1l);
    cudaGetSymbolAddress((void**)&pwih, g_wih); cudaGetSymbolAddress((void**)&pwil, g_wil);
    cudaGetSymbolAddress((void**)&pwoh, g_woh); cudaGetSymbolAddress((void**)&pwol, g_wol);
    cudaGetSymbolAddress((void**)&pw1h, g_w1h); cudaGetSymbolAddress((void**)&pw1l, g_w1l);
    cudaGetSymbolAddress((void**)&pw2h, g_w2h); cudaGetSymbolAddress((void**)&pw2l, g_w2l);

    dim3 lnb(32, 8);
    // weight pre-split (cheap; runs once per call)
    wsplit_kernel<<<384, 256>>>(in_w,  pwih, pwil, 3 * DMODEL * DMODEL / 2);
    wsplit_kernel<<<128, 256>>>(out_w, pwoh, pwol, DMODEL * DMODEL / 2);
    wsplit_kernel<<<512, 256>>>(w1,    pw1h, pw1l, DFF * DMODEL / 2);
    wsplit_kernel<<<512, 256>>>(w2,    pw2h, pw2l, DMODEL * DFF / 2);
    // 1. x = LN1(src) -> pair
    ln_kernel<false><<<MROWS / 8, lnb>>>(src, nullptr, nullptr, g1, be1, pxh, pxl);
    // 2. qkv GEMM -> q/k (std pairs) + v (transposed pairs)
    gemm_pair_kernel<3, 128><<<dim3(6, 64), 256>>>(
        pxh, pxl, pwih, pwil, in_b, nullptr, nullptr, nullptr, nullptr, nullptr,
        pqh, pql, pkh, pkl, pvth, pvtl, DMODEL, 3 * DMODEL);
    // 3. flash attention -> ctx pair
    attn_pair_kernel<<<dim3(8, 64), 256>>>(pqh, pql, pkh, pkl, pvth, pvtl, bias, pch, pcl);
    // 4. x2 = x + ctx @ out_w^T + out_b -> pair
    gemm_pair_kernel<2, 64><<<dim3(4, 64), 256>>>(
        pch, pcl, pwoh, pwol, out_b, pxh, pxl, px2h, px2l, nullptr,
        nullptr, nullptr, nullptr, nullptr, nullptr, nullptr, DMODEL, DMODEL);
    // 5. y = LN2(x2) -> pair
    ln_kernel<true><<<MROWS / 8, lnb>>>(nullptr, px2h, px2l, g2, be2, pyh, pyl);
    // 6. ff1 = relu(y @ w1^T + b1) -> pair
    gemm_pair_kernel<1, 128><<<dim3(8, 64), 256>>>(
        pyh, pyl, pw1h, pw1l, b1, nullptr, nullptr, pf1h, pf1l, nullptr,
        nullptr, nullptr, nullptr, nullptr, nullptr, nullptr, DMODEL, DFF);
    // 7. out = y + ff1 @ w2^T + b2 -> fp32 d_out
    gemm_pair_kernel<4, 64><<<dim3(4, 64), 256>>>(
        pf1h, pf1l, pw2h, pw2l, b2, pyh, pyl, nullptr, nullptr, out,
        nullptr, nullptr, nullptr, nullptr, nullptr, nullptr, DFF, DMODEL);
}

// round 8
// speedup vs baseline: 1.0044x; 1.0044x over previous
#include <cuda_runtime.h>
#include <cuda_bf16.h>
#include <cstdint>
#include <math.h>

#define S_LEN  1024
#define BATCH  8
#define DMODEL 256
#define NH     8
#define HDIM   32
#define DFF    1024
#define MROWS  (S_LEN * BATCH)   // 8192
#define LN_EPS 1e-5f

// ---------------- scratch (no runtime allocation allowed) ----------------
__device__ float g_x  [MROWS * DMODEL];
__device__ float g_q  [BATCH * NH * S_LEN * HDIM];
__device__ float g_k  [BATCH * NH * S_LEN * HDIM];
__device__ float g_v  [BATCH * NH * S_LEN * HDIM];
__device__ float g_ctx[MROWS * DMODEL];
__device__ float g_x2 [MROWS * DMODEL];
__device__ float g_y  [MROWS * DMODEL];
__device__ float g_ff1[MROWS * DFF];

// ---------------- helpers --------------------------------------------------
__device__ __forceinline__ uint32_t smem_u32(const void* p) {
    uint32_t a;
    asm("{ .reg .u64 t; cvta.to.shared.u64 t, %1; cvt.u32.u64 %0, t; }" : "=r"(a) : "l"(p));
    return a;
}
__device__ __forceinline__ void cp_async16(uint32_t s, const void* g) {
    asm volatile("cp.async.cg.shared.global [%0], [%1], 16;" :: "r"(s), "l"(g));
}
#define CP_COMMIT() asm volatile("cp.async.commit_group;" ::: "memory")
#define CP_WAIT1()  asm volatile("cp.async.wait_group 1;" ::: "memory")
#define CP_WAIT0()  asm volatile("cp.async.wait_group 0;" ::: "memory")

__device__ __forceinline__ void mma16816(float* c, const uint32_t* a, uint32_t b0, uint32_t b1) {
    asm volatile(
        "mma.sync.aligned.m16n8k16.row.col.f32.bf16.bf16.f32 "
        "{%0,%1,%2,%3}, {%4,%5,%6,%7}, {%8,%9}, {%0,%1,%2,%3};"
        : "+f"(c[0]), "+f"(c[1]), "+f"(c[2]), "+f"(c[3])
        : "r"(a[0]), "r"(a[1]), "r"(a[2]), "r"(a[3]), "r"(b0), "r"(b1));
}
__device__ __forceinline__ void split_bf16x2(float x, float y, uint32_t& hi, uint32_t& lo) {
    __nv_bfloat162 h = __floats2bfloat162_rn(x, y);
    float hx = __bfloat162float(h.x), hy = __bfloat162float(h.y);
    __nv_bfloat162 l = __floats2bfloat162_rn(x - hx, y - hy);
    hi = *reinterpret_cast<uint32_t*>(&h);
    lo = *reinterpret_cast<uint32_t*>(&l);
}

// ---------------- LayerNorm: one warp per row (round-6 proven) ------------
__global__ void ln_kernel(const float* __restrict__ in,
                          const float* __restrict__ gw,
                          const float* __restrict__ bw,
                          float* __restrict__ out) {
    int row  = blockIdx.x * blockDim.y + threadIdx.y;
    int lane = threadIdx.x;
    const float4* xp = (const float4*)(in + (size_t)row * DMODEL);
    float4 v0 = xp[lane];
    float4 v1 = xp[lane + 32];
    float s = v0.x + v0.y + v0.z + v0.w + v1.x + v1.y + v1.z + v1.w;
#pragma unroll
    for (int o = 16; o > 0; o >>= 1) s += __shfl_xor_sync(0xffffffffu, s, o);
    float mu = s * (1.0f / DMODEL);
    float d0x = v0.x - mu, d0y = v0.y - mu, d0z = v0.z - mu, d0w = v0.w - mu;
    float d1x = v1.x - mu, d1y = v1.y - mu, d1z = v1.z - mu, d1w = v1.w - mu;
    float q = d0x*d0x + d0y*d0y + d0z*d0z + d0w*d0w
            + d1x*d1x + d1y*d1y + d1z*d1z + d1w*d1w;
#pragma unroll
    for (int o = 16; o > 0; o >>= 1) q += __shfl_xor_sync(0xffffffffu, q, o);
    float rs = rsqrtf(q * (1.0f / DMODEL) + LN_EPS);
    const float4* gp = (const float4*)gw;
    const float4* bp = (const float4*)bw;
    float4 ga = gp[lane], gb = gp[lane + 32];
    float4 ba = bp[lane], bb = bp[lane + 32];
    float4 o0, o1;
    o0.x = d0x * rs * ga.x + ba.x;  o0.y = d0y * rs * ga.y + ba.y;
    o0.z = d0z * rs * ga.z + ba.z;  o0.w = d0w * rs * ga.w + ba.w;
    o1.x = d1x * rs * gb.x + bb.x;  o1.y = d1y * rs * gb.y + bb.y;
    o1.z = d1z * rs * gb.z + bb.z;  o1.w = d1w * rs * gb.w + bb.w;
    float4* op = (float4*)(out + (size_t)row * DMODEL);
    op[lane]      = o0;
    op[lane + 32] = o1;
}

// ================= cp.async double-buffered bf16-split GEMM ===============
// C[M,N] = A[M,K] @ W[N,K]^T. fp32 tiles staged via cp.async (ping-pong),
// split to bf16 hi/lo at fragment-load time. Block 128 x BN, BK=32,
// 256 threads = 8 warps (4m x 2n). MODE: 1 relu, 2 resid, 3 qkv scatter.
#define SP 36   // fp32 smem row pitch (32 used; 16B-aligned; conflict-light)
template<int MODE, int BN>
__global__ void __launch_bounds__(256, 2) gemm_cp_kernel(
    const float* __restrict__ A, const float* __restrict__ W,
    const float* __restrict__ bias, const float* __restrict__ resid,
    float* __restrict__ C,
    float* __restrict__ qo, float* __restrict__ ko, float* __restrict__ vo,
    int K, int N)
{
    constexpr int NT = BN / 16;               // n-tiles per warp
    extern __shared__ float sm[];
    float* sA = sm;                            // [2][128*SP]
    float* sW = sm + 2 * 128 * SP;             // [2][BN*SP]
    uint32_t sb = smem_u32(sm);
    const uint32_t aByte = 128 * SP * 4;
    const uint32_t wBase = 2 * aByte;
    const uint32_t wByte = BN * SP * 4;

    int tid = threadIdx.x;
    int warp = tid >> 5, lane = tid & 31;
    int g = lane >> 2, q4 = lane & 3;
    int wm = warp >> 1, wn = warp & 1;
    int m0 = wm * 32, n0 = wn * (BN / 2);
    int rowBase = blockIdx.y * 128;
    int colBase = blockIdx.x * BN;

    // staging maps
    int lrA = tid >> 1, caA = (tid & 1) * 16;              // 16 floats (4x16B)
    const float* Ag = A + (size_t)(rowBase + lrA) * K + caA;
    uint32_t dstA0 = sb + (lrA * SP + caA) * 4;
    int lrW, caW;
    if (BN == 128) { lrW = tid >> 1; caW = (tid & 1) * 16; }
    else           { lrW = tid >> 2; caW = (tid & 3) * 8; }
    const float* Wg = W + (size_t)(colBase + lrW) * K + caW;
    uint32_t dstW0 = sb + wBase + (lrW * SP + caW) * 4;

    float c[2][NT][4];
#pragma unroll
    for (int mt = 0; mt < 2; mt++)
#pragma unroll
        for (int nt = 0; nt < NT; nt++)
#pragma unroll
            for (int i = 0; i < 4; i++) c[mt][nt][i] = 0.0f;

    int iters = K >> 5;
    // prime: stage tile 0 into buffer 0
    {
        uint32_t dA = dstA0, dW = dstW0;
        cp_async16(dA, Ag);      cp_async16(dA + 16, Ag + 4);
        cp_async16(dA + 32, Ag + 8); cp_async16(dA + 48, Ag + 12);
        cp_async16(dW, Wg);      cp_async16(dW + 16, Wg + 4);
        if (BN == 128) { cp_async16(dW + 32, Wg + 8); cp_async16(dW + 48, Wg + 12); }
        CP_COMMIT();
    }

    for (int it = 0; it < iters; it++) {
        int cur = it & 1;
        if (it + 1 < iters) {
            int nb = (it + 1) & 1;
            const float* An = Ag + (it + 1) * 32;
            const float* Wn = Wg + (it + 1) * 32;
            uint32_t dA = dstA0 + nb * aByte, dW = dstW0 + nb * wByte;
            cp_async16(dA, An);      cp_async16(dA + 16, An + 4);
            cp_async16(dA + 32, An + 8); cp_async16(dA + 48, An + 12);
            cp_async16(dW, Wn);      cp_async16(dW + 16, Wn + 4);
            if (BN == 128) { cp_async16(dW + 32, Wn + 8); cp_async16(dW + 48, Wn + 12); }
            CP_COMMIT();
            CP_WAIT1();
        } else {
            CP_WAIT0();
        }
        __syncthreads();

        const float* As = sA + cur * 128 * SP;
        const float* Ws = sW + cur * BN * SP;
#pragma unroll
        for (int ks = 0; ks < 2; ks++) {
            int kb = ks * 16 + 2 * q4;
            uint32_t ah[2][4], al[2][4];
#pragma unroll
            for (int mt = 0; mt < 2; mt++) {
                int r0 = (m0 + mt * 16 + g) * SP + kb;
                int r1 = r0 + 8 * SP;
                float2 x0 = *(const float2*)&As[r0];
                float2 x1 = *(const float2*)&As[r1];
                float2 x2 = *(const float2*)&As[r0 + 8];
                float2 x3 = *(const float2*)&As[r1 + 8];
                split_bf16x2(x0.x, x0.y, ah[mt][0], al[mt][0]);
                split_bf16x2(x1.x, x1.y, ah[mt][1], al[mt][1]);
                split_bf16x2(x2.x, x2.y, ah[mt][2], al[mt][2]);
                split_bf16x2(x3.x, x3.y, ah[mt][3], al[mt][3]);
            }
#pragma unroll
            for (int nt = 0; nt < NT; nt++) {
                int rw = (n0 + nt * 8 + g) * SP + kb;
                float2 w0 = *(const float2*)&Ws[rw];
                float2 w1 = *(const float2*)&Ws[rw + 8];
                uint32_t bh0, bl0, bh1, bl1;
                split_bf16x2(w0.x, w0.y, bh0, bl0);
                split_bf16x2(w1.x, w1.y, bh1, bl1);
#pragma unroll
                for (int mt = 0; mt < 2; mt++) {
                    mma16816(c[mt][nt], ah[mt], bh0, bh1);
                    mma16816(c[mt][nt], ah[mt], bl0, bl1);
                    mma16816(c[mt][nt], al[mt], bh0, bh1);
                }
            }
        }
        __syncthreads();
    }

    // ---- epilogue (round-6 semantics) ----
#pragma unroll
    for (int mt = 0; mt < 2; mt++) {
#pragma unroll
        for (int half = 0; half < 2; half++) {
            int r = rowBase + m0 + mt * 16 + g + half * 8;
#pragma unroll
            for (int nt = 0; nt < NT; nt++) {
                int cc = colBase + n0 + nt * 8 + 2 * q4;
                float v0 = c[mt][nt][half * 2 + 0] + bias[cc];
                float v1 = c[mt][nt][half * 2 + 1] + bias[cc + 1];
                if (MODE == 1) { v0 = fmaxf(v0, 0.0f); v1 = fmaxf(v1, 0.0f); }
                if (MODE == 2) {
                    float2 rr = *(const float2*)&resid[(size_t)r * N + cc];
                    v0 += rr.x; v1 += rr.y;
                }
                if (MODE == 3) {
                    int s = r >> 3, b = r & 7;
                    int part = cc >> 8;
                    int h = (cc & 255) >> 5;
                    int hd = cc & 31;
                    size_t dst = ((((size_t)b * NH + h) * S_LEN + s) * HDIM) + hd;
                    if (part == 0) {
                        const float sc = 0.17677669529663687f;  // 1/sqrt(32)
                        *(float2*)&qo[dst] = make_float2(v0 * sc, v1 * sc);
                    } else if (part == 1) {
                        *(float2*)&ko[dst] = make_float2(v0, v1);
                    } else {
                        *(float2*)&vo[dst] = make_float2(v0, v1);
                    }
                } else {
                    *(float2*)&C[(size_t)r * N + cc] = make_float2(v0, v1);
                }
            }
        }
    }
}

// ================= cp.async bf16-split flash attention =====================
// Round-6 core; K/V chunks stream into fp32 staging (ping-pong) via cp.async,
// convert-to-split happens off the DRAM latency path.
#define PK 20    // split-K pitch (uint32; 16 used)
#define PV2 36   // split-V^T pitch (uint32; 32 used)
#define A_SKH 0
#define A_SKL (A_SKH + 64 * PK)
#define A_SVH (A_SKL + 64 * PK)
#define A_SVL (A_SVH + 32 * PV2)
#define A_STK (A_SVL + 32 * PV2)            // float [2][64*SP]
#define A_STV (A_STK + 2 * 64 * SP)         // float [2][64*SP]
#define A_TOT_U32 (A_STV + 2 * 64 * SP)
#define A_TOT_BYTES (A_TOT_U32 * 4)         // 56320

__global__ void __launch_bounds__(256, 2) attn_cp_kernel(
    const float* __restrict__ Qg, const float* __restrict__ Kg,
    const float* __restrict__ Vg, const float* __restrict__ biasg,
    float* __restrict__ ctx)
{
    extern __shared__ uint32_t asmem[];
    uint32_t* sKh = asmem + A_SKH;
    uint32_t* sKl = asmem + A_SKL;
    uint32_t* sVh = asmem + A_SVH;
    uint32_t* sVl = asmem + A_SVL;
    float* stK = (float*)(asmem + A_STK);
    float* stV = (float*)(asmem + A_STV);
    uint32_t sb = smem_u32(asmem);

    int tid  = threadIdx.x;
    int warp = tid >> 5, lane = tid & 31;
    int g = lane >> 2, q4 = lane & 3;
    int bh = blockIdx.y, qt = blockIdx.x;
    int b = bh >> 3, h = bh & 7;
    int rA = warp * 16 + g;
    int rB = rA + 8;

    const float* qb = Qg + ((size_t)bh * S_LEN + (size_t)qt * 128) * HDIM;
    const float* kb = Kg + (size_t)bh * S_LEN * HDIM;
    const float* vb = Vg + (size_t)bh * S_LEN * HDIM;
    const float* biasA = biasg + ((size_t)bh * S_LEN + (size_t)(qt * 128 + rA)) * S_LEN;
    const float* biasB = biasA + (size_t)8 * S_LEN;

    // ---- Q fragments (split once, held in regs) ----
    uint32_t qh[2][4], ql[2][4];
#pragma unroll
    for (int kt = 0; kt < 2; kt++) {
        int k0 = kt * 16 + 2 * q4;
        split_bf16x2(qb[rA * HDIM + k0],     qb[rA * HDIM + k0 + 1], qh[kt][0], ql[kt][0]);
        split_bf16x2(qb[rB * HDIM + k0],     qb[rB * HDIM + k0 + 1], qh[kt][1], ql[kt][1]);
        split_bf16x2(qb[rA * HDIM + k0 + 8], qb[rA * HDIM + k0 + 9], qh[kt][2], ql[kt][2]);
        split_bf16x2(qb[rB * HDIM + k0 + 8], qb[rB * HDIM + k0 + 9], qh[kt][3], ql[kt][3]);
    }

    float mA = -1e30f, mB = -1e30f, lA = 0.0f, lB = 0.0f;
    float o[4][4];
#pragma unroll
    for (int nt = 0; nt < 4; nt++)
#pragma unroll
        for (int i = 0; i < 4; i++) o[nt][i] = 0.0f;

    // maps: staging (cp.async): tS = tid>>2 (0..63), cS = (tid&3)*8 floats
    //       convert K: same; convert V: uV = tid>>3 (0..31), dV = (tid&7)*4
    int tS = tid >> 2, cS = (tid & 3) * 8;
    int uV = tid >> 3, dV = (tid & 7) * 4;
    uint32_t dstK0 = sb + A_STK * 4 + (tS * SP + cS) * 4;
    uint32_t dstV0 = sb + A_STV * 4 + (tS * SP + cS) * 4;
    const uint32_t chunkB = 64 * SP * 4;

    // prime chunk 0
    {
        const float* ks = kb + (size_t)tS * HDIM + cS;
        const float* vs = vb + (size_t)tS * HDIM + cS;
        cp_async16(dstK0, ks); cp_async16(dstK0 + 16, ks + 4);
        cp_async16(dstV0, vs); cp_async16(dstV0 + 16, vs + 4);
        CP_COMMIT();
    }

    for (int j = 0; j < 16; j++) {
        if (j + 1 < 16) {
            int nb = (j + 1) & 1;
            const float* ks = kb + (size_t)((j + 1) * 64 + tS) * HDIM + cS;
            const float* vs = vb + (size_t)((j + 1) * 64 + tS) * HDIM + cS;
            cp_async16(dstK0 + nb * chunkB, ks); cp_async16(dstK0 + nb * chunkB + 16, ks + 4);
            cp_async16(dstV0 + nb * chunkB, vs); cp_async16(dstV0 + nb * chunkB + 16, vs + 4);
            CP_COMMIT();
            CP_WAIT1();
        } else {
            CP_WAIT0();
        }
        __syncthreads();   // chunk j staged; also: all threads done with split smem of j-1

        // ---- convert staging -> split smem ----
        {
            const float* sk = stK + (j & 1) * 64 * SP + tS * SP + cS;
            uint32_t* kh = sKh + tS * PK + (cS >> 1);
            uint32_t* kl = sKl + tS * PK + (cS >> 1);
            uint32_t hh, ll;
            split_bf16x2(sk[0], sk[1], hh, ll); kh[0] = hh; kl[0] = ll;
            split_bf16x2(sk[2], sk[3], hh, ll); kh[1] = hh; kl[1] = ll;
            split_bf16x2(sk[4], sk[5], hh, ll); kh[2] = hh; kl[2] = ll;
            split_bf16x2(sk[6], sk[7], hh, ll); kh[3] = hh; kl[3] = ll;

            const float* sv = stV + (j & 1) * 64 * SP;
            float4 v0 = *(const float4*)&sv[(2 * uV) * SP + dV];
            float4 v1 = *(const float4*)&sv[(2 * uV + 1) * SP + dV];
            split_bf16x2(v0.x, v1.x, hh, ll); sVh[(dV + 0) * PV2 + uV] = hh; sVl[(dV + 0) * PV2 + uV] = ll;
            split_bf16x2(v0.y, v1.y, hh, ll); sVh[(dV + 1) * PV2 + uV] = hh; sVl[(dV + 1) * PV2 + uV] = ll;
            split_bf16x2(v0.z, v1.z, hh, ll); sVh[(dV + 2) * PV2 + uV] = hh; sVl[(dV + 2) * PV2 + uV] = ll;
            split_bf16x2(v0.w, v1.w, hh, ll); sVh[(dV + 3) * PV2 + uV] = hh; sVl[(dV + 3) * PV2 + uV] = ll;
        }
        __syncthreads();

        // ---- C init with bias (read once from DRAM) ----
        float c[8][4];
#pragma unroll
        for (int nt = 0; nt < 8; nt++) {
            float2 bA = *(const float2*)(biasA + j * 64 + nt * 8 + 2 * q4);
            float2 bB = *(const float2*)(biasB + j * 64 + nt * 8 + 2 * q4);
            c[nt][0] = bA.x; c[nt][1] = bA.y; c[nt][2] = bB.x; c[nt][3] = bB.y;
        }

        // ---- QK^T ----
#pragma unroll
        for (int nt = 0; nt < 8; nt++) {
#pragma unroll
            for (int kt = 0; kt < 2; kt++) {
                int rb = (nt * 8 + g) * PK + kt * 8 + q4;
                uint32_t bh0 = sKh[rb], bh1 = sKh[rb + 4];
                uint32_t bl0 = sKl[rb], bl1 = sKl[rb + 4];
                mma16816(c[nt], qh[kt], bh0, bh1);
                mma16816(c[nt], qh[kt], bl0, bl1);
                mma16816(c[nt], ql[kt], bh0, bh1);
            }
        }

        // ---- online softmax ----
        float mxA = -1e30f, mxB = -1e30f;
#pragma unroll
        for (int nt = 0; nt < 8; nt++) {
            mxA = fmaxf(mxA, fmaxf(c[nt][0], c[nt][1]));
            mxB = fmaxf(mxB, fmaxf(c[nt][2], c[nt][3]));
        }
        mxA = fmaxf(mxA, __shfl_xor_sync(0xffffffffu, mxA, 1));
        mxA = fmaxf(mxA, __shfl_xor_sync(0xffffffffu, mxA, 2));
        mxB = fmaxf(mxB, __shfl_xor_sync(0xffffffffu, mxB, 1));
        mxB = fmaxf(mxB, __shfl_xor_sync(0xffffffffu, mxB, 2));
        float nmA = fmaxf(mA, mxA), nmB = fmaxf(mB, mxB);
        float corrA = __expf(mA - nmA), corrB = __expf(mB - nmB);
        mA = nmA; mB = nmB;
        float sA2 = 0.0f, sB2 = 0.0f;
#pragma unroll
        for (int nt = 0; nt < 8; nt++) {
            c[nt][0] = __expf(c[nt][0] - nmA);
            c[nt][1] = __expf(c[nt][1] - nmA);
            c[nt][2] = __expf(c[nt][2] - nmB);
            c[nt][3] = __expf(c[nt][3] - nmB);
            sA2 += c[nt][0] + c[nt][1];
            sB2 += c[nt][2] + c[nt][3];
        }
        sA2 += __shfl_xor_sync(0xffffffffu, sA2, 1);
        sA2 += __shfl_xor_sync(0xffffffffu, sA2, 2);
        sB2 += __shfl_xor_sync(0xffffffffu, sB2, 1);
        sB2 += __shfl_xor_sync(0xffffffffu, sB2, 2);
        lA = lA * corrA + sA2;
        lB = lB * corrB + sB2;
#pragma unroll
        for (int nt = 0; nt < 4; nt++) {
            o[nt][0] *= corrA; o[nt][1] *= corrA;
            o[nt][2] *= corrB; o[nt][3] *= corrB;
        }

        // ---- repack P (C-frag == PV A-frag layout), split hi/lo ----
        uint32_t ph[4][4], pl[4][4];
#pragma unroll
        for (int kk = 0; kk < 4; kk++) {
            split_bf16x2(c[2 * kk][0],     c[2 * kk][1],     ph[kk][0], pl[kk][0]);
            split_bf16x2(c[2 * kk][2],     c[2 * kk][3],     ph[kk][1], pl[kk][1]);
            split_bf16x2(c[2 * kk + 1][0], c[2 * kk + 1][1], ph[kk][2], pl[kk][2]);
            split_bf16x2(c[2 * kk + 1][2], c[2 * kk + 1][3], ph[kk][3], pl[kk][3]);
        }

        // ---- PV ----
#pragma unroll
        for (int kk = 0; kk < 4; kk++) {
#pragma unroll
            for (int nt = 0; nt < 4; nt++) {
                int rb = (nt * 8 + g) * PV2 + kk * 8 + q4;
                uint32_t bh0 = sVh[rb], bh1 = sVh[rb + 4];
                uint32_t bl0 = sVl[rb], bl1 = sVl[rb + 4];
                mma16816(o[nt], ph[kk], bh0, bh1);
                mma16816(o[nt], ph[kk], bl0, bl1);
                mma16816(o[nt], pl[kk], bh0, bh1);
            }
        }
        // no trailing sync: next iteration's post-wait __syncthreads() orders
        // split-smem overwrite after all reads of this chunk.
    }

    // ---- epilogue: normalize, write ctx[S,B,D] ----
    float invA = 1.0f / lA, invB = 1.0f / lB;
    float* cA = ctx + ((size_t)(qt * 128 + rA) * BATCH + b) * DMODEL + h * HDIM;
    float* cB = ctx + ((size_t)(qt * 128 + rB) * BATCH + b) * DMODEL + h * HDIM;
#pragma unroll
    for (int nt = 0; nt < 4; nt++) {
        *(float2*)(cA + nt * 8 + 2 * q4) = make_float2(o[nt][0] * invA, o[nt][1] * invA);
        *(float2*)(cB + nt * 8 + 2 * q4) = make_float2(o[nt][2] * invB, o[nt][3] * invB);
    }
}

// ---------------- launch ---------------------------------------------------
extern "C" void kernel_launch(void* const* d_in, const int* in_sizes, int n_in,
                              void* d_out, int out_size) {
    const float* src   = (const float*)d_in[0];
    const float* bias  = (const float*)d_in[1];
    const float* in_w  = (const float*)d_in[2];
    const float* in_b  = (const float*)d_in[3];
    const float* out_w = (const float*)d_in[4];
    const float* out_b = (const float*)d_in[5];
    const float* w1    = (const float*)d_in[6];
    const float* b1    = (const float*)d_in[7];
    const float* w2    = (const float*)d_in[8];
    const float* b2    = (const float*)d_in[9];
    const float* g1    = (const float*)d_in[10];
    const float* be1   = (const float*)d_in[11];
    const float* g2    = (const float*)d_in[12];
    const float* be2   = (const float*)d_in[13];
    float* out = (float*)d_out;

    float *px, *pq, *pk, *pv, *pctx, *px2, *py, *pff1;
    cudaGetSymbolAddress((void**)&px,   g_x);
    cudaGetSymbolAddress((void**)&pq,   g_q);
    cudaGetSymbolAddress((void**)&pk,   g_k);
    cudaGetSymbolAddress((void**)&pv,   g_v);
    cudaGetSymbolAddress((void**)&pctx, g_ctx);
    cudaGetSymbolAddress((void**)&px2,  g_x2);
    cudaGetSymbolAddress((void**)&py,   g_y);
    cudaGetSymbolAddress((void**)&pff1, g_ff1);

    // dynamic smem sizes (bytes)
    const int smem128 = (2 * 128 * SP + 2 * 128 * SP) * 4;   // 73728
    const int smem64  = (2 * 128 * SP + 2 * 64 * SP) * 4;    // 55296
    cudaFuncSetAttribute(gemm_cp_kernel<3, 128>, cudaFuncAttributeMaxDynamicSharedMemorySize, smem128);
    cudaFuncSetAttribute(gemm_cp_kernel<1, 128>, cudaFuncAttributeMaxDynamicSharedMemorySize, smem128);
    cudaFuncSetAttribute(gemm_cp_kernel<2, 64>,  cudaFuncAttributeMaxDynamicSharedMemorySize, smem64);
    cudaFuncSetAttribute(attn_cp_kernel, cudaFuncAttributeMaxDynamicSharedMemorySize, A_TOT_BYTES);

    dim3 lnb(32, 8);
    // 1. x = LN1(src)
    ln_kernel<<<MROWS / 8, lnb>>>(src, g1, be1, px);
    // 2. qkv = x @ in_w^T + in_b -> scattered q/k/v head layout
    gemm_cp_kernel<3, 128><<<dim3(6, 64), 256, smem128>>>(
        px, in_w, in_b, nullptr, nullptr, pq, pk, pv, DMODEL, 3 * DMODEL);
    // 3. flash attention with bias -> ctx [S,B,D]
    attn_cp_kernel<<<dim3(8, 64), 256, A_TOT_BYTES>>>(pq, pk, pv, bias, pctx);
    // 4. x2 = x + ctx @ out_w^T + out_b
    gemm_cp_kernel<2, 64><<<dim3(4, 64), 256, smem64>>>(
        pctx, out_w, out_b, px, px2, nullptr, nullptr, nullptr, DMODEL, DMODEL);
    // 5. y = LN2(x2)
    ln_kernel<<<MROWS / 8, lnb>>>(px2, g2, be2, py);
    // 6. ff1 = relu(y @ w1^T + b1)
    gemm_cp_kernel<1, 128><<<dim3(8, 64), 256, smem128>>>(
        py, w1, b1, nullptr, pff1, nullptr, nullptr, nullptr, DMODEL, DFF);
    // 7. out = y + ff1 @ w2^T + b2
    gemm_cp_kernel<2, 64><<<dim3(4, 64), 256, smem64>>>(
        pff1, w2, b2, py, out, nullptr, nullptr, nullptr, DFF, DMODEL);
}

// round 10
// speedup vs baseline: 1.0570x; 1.0523x over previous
#include <cuda_runtime.h>
#include <cuda_bf16.h>
#include <cstdint>
#include <math.h>

#define S_LEN  1024
#define BATCH  8
#define DMODEL 256
#define NH     8
#define HDIM   32
#define DFF    1024
#define MROWS  (S_LEN * BATCH)   // 8192
#define LN_EPS 1e-5f

// ---------------- scratch (no runtime allocation allowed) ----------------
__device__ float g_x  [MROWS * DMODEL];
__device__ float g_q  [BATCH * NH * S_LEN * HDIM];
__device__ float g_k  [BATCH * NH * S_LEN * HDIM];
__device__ float g_v  [BATCH * NH * S_LEN * HDIM];
__device__ float g_ctx[MROWS * DMODEL];
__device__ float g_x2 [MROWS * DMODEL];
__device__ float g_y  [MROWS * DMODEL];
__device__ float g_ff1[MROWS * DFF];

// ---------------- helpers --------------------------------------------------
__device__ __forceinline__ uint32_t smem_u32(const void* p) {
    uint32_t a;
    asm("{ .reg .u64 t; cvta.to.shared.u64 t, %1; cvt.u32.u64 %0, t; }" : "=r"(a) : "l"(p));
    return a;
}
__device__ __forceinline__ void mma16816(float* c, const uint32_t* a, uint32_t b0, uint32_t b1) {
    asm volatile(
        "mma.sync.aligned.m16n8k16.row.col.f32.bf16.bf16.f32 "
        "{%0,%1,%2,%3}, {%4,%5,%6,%7}, {%8,%9}, {%0,%1,%2,%3};"
        : "+f"(c[0]), "+f"(c[1]), "+f"(c[2]), "+f"(c[3])
        : "r"(a[0]), "r"(a[1]), "r"(a[2]), "r"(a[3]), "r"(b0), "r"(b1));
}
__device__ __forceinline__ void ldsm_x4(uint32_t* r, uint32_t addr) {
    asm volatile("ldmatrix.sync.aligned.m8n8.x4.shared.b16 {%0,%1,%2,%3}, [%4];"
        : "=r"(r[0]), "=r"(r[1]), "=r"(r[2]), "=r"(r[3]) : "r"(addr));
}
__device__ __forceinline__ void split_bf16x2(float x, float y, uint32_t& hi, uint32_t& lo) {
    __nv_bfloat162 h = __floats2bfloat162_rn(x, y);
    float hx = __bfloat162float(h.x), hy = __bfloat162float(h.y);
    __nv_bfloat162 l = __floats2bfloat162_rn(x - hx, y - hy);
    hi = *reinterpret_cast<uint32_t*>(&h);
    lo = *reinterpret_cast<uint32_t*>(&l);
}

// ---------------- LayerNorm: one warp per row (proven) --------------------
__global__ void ln_kernel(const float* __restrict__ in,
                          const float* __restrict__ gw,
                          const float* __restrict__ bw,
                          float* __restrict__ out) {
    int row  = blockIdx.x * blockDim.y + threadIdx.y;
    int lane = threadIdx.x;
    const float4* xp = (const float4*)(in + (size_t)row * DMODEL);
    float4 v0 = xp[lane];
    float4 v1 = xp[lane + 32];
    float s = v0.x + v0.y + v0.z + v0.w + v1.x + v1.y + v1.z + v1.w;
#pragma unroll
    for (int o = 16; o > 0; o >>= 1) s += __shfl_xor_sync(0xffffffffu, s, o);
    float mu = s * (1.0f / DMODEL);
    float d0x = v0.x - mu, d0y = v0.y - mu, d0z = v0.z - mu, d0w = v0.w - mu;
    float d1x = v1.x - mu, d1y = v1.y - mu, d1z = v1.z - mu, d1w = v1.w - mu;
    float q = d0x*d0x + d0y*d0y + d0z*d0z + d0w*d0w
            + d1x*d1x + d1y*d1y + d1z*d1z + d1w*d1w;
#pragma unroll
    for (int o = 16; o > 0; o >>= 1) q += __shfl_xor_sync(0xffffffffu, q, o);
    float rs = rsqrtf(q * (1.0f / DMODEL) + LN_EPS);
    const float4* gp = (const float4*)gw;
    const float4* bp = (const float4*)bw;
    float4 ga = gp[lane], gb = gp[lane + 32];
    float4 ba = bp[lane], bb = bp[lane + 32];
    float4 o0, o1;
    o0.x = d0x * rs * ga.x + ba.x;  o0.y = d0y * rs * ga.y + ba.y;
    o0.z = d0z * rs * ga.z + ba.z;  o0.w = d0w * rs * ga.w + ba.w;
    o1.x = d1x * rs * gb.x + bb.x;  o1.y = d1y * rs * gb.y + bb.y;
    o1.z = d1z * rs * gb.z + bb.z;  o1.w = d1w * rs * gb.w + bb.w;
    float4* op = (float4*)(out + (size_t)row * DMODEL);
    op[lane]      = o0;
    op[lane + 32] = o1;
}

// ================= ldmatrix bf16-split tensor GEMM =========================
// C[M,N] = A[M,K] @ W[N,K]^T. Tiles split to bf16 hi/lo at staging (once),
// fragments fetched via ldmatrix.x4. Block 128 x BN, BK=32, 256 thr = 8 warps.
// Pitch PT=20 u32 = 80B: every row 16B-aligned (ldmatrix requirement) AND
// 8-row ldmatrix start banks r*20 mod 32 = {0,20,8,28,16,4,24,12} (conflict-free).
// MODE: 1 = bias+relu, 2 = bias+resid, 3 = qkv scatter (+q scale)
#define PT 20
template<int MODE, int BN>
__global__ void __launch_bounds__(256) gemm_ldsm_kernel(
    const float* __restrict__ A, const float* __restrict__ W,
    const float* __restrict__ bias, const float* __restrict__ resid,
    float* __restrict__ C,
    float* __restrict__ qo, float* __restrict__ ko, float* __restrict__ vo,
    int K, int N)
{
    constexpr int NT = BN / 16;               // n-tiles per warp
    __shared__ uint32_t sAh[128 * PT], sAl[128 * PT];
    __shared__ uint32_t sWh[BN * PT],  sWl[BN * PT];

    int tid = threadIdx.x;
    int warp = tid >> 5, lane = tid & 31;
    int g = lane >> 2, q4 = lane & 3;
    int wm = warp >> 1, wn = warp & 1;
    int m0 = wm * 32, n0 = wn * (BN / 2);
    int rowBase = blockIdx.y * 128;
    int colBase = blockIdx.x * BN;

    // staging maps
    int lrA = tid >> 1, lcA = (tid & 1) * 16;              // 16 floats of one row
    const float* Ap = A + (size_t)(rowBase + lrA) * K + lcA;
    uint32_t* sAhp = sAh + lrA * PT + (tid & 1) * 8;
    uint32_t* sAlp = sAl + lrA * PT + (tid & 1) * 8;
    int lrW, lcW, wuo;
    if (BN == 128) { lrW = tid >> 1; lcW = (tid & 1) * 16; wuo = (tid & 1) * 8; }
    else           { lrW = tid >> 2; lcW = (tid & 3) * 8;  wuo = (tid & 3) * 4; }
    const float* Wp = W + (size_t)(colBase + lrW) * K + lcW;
    uint32_t* sWhp = sWh + lrW * PT + wuo;
    uint32_t* sWlp = sWl + lrW * PT + wuo;

    // ldmatrix per-lane base addresses (bytes)
    uint32_t aRow = (uint32_t)(m0 + (lane & 7) + ((lane >> 3) & 1) * 8);
    uint32_t aCol = (uint32_t)((lane >> 4) * 4);
    uint32_t aHi = smem_u32(sAh) + (aRow * PT + aCol) * 4;
    uint32_t aLo = smem_u32(sAl) + (aRow * PT + aCol) * 4;
    uint32_t wRow = (uint32_t)(n0 + (lane & 7));
    uint32_t wCol = (uint32_t)((lane >> 3) * 4);
    uint32_t wHi = smem_u32(sWh) + (wRow * PT + wCol) * 4;
    uint32_t wLo = smem_u32(sWl) + (wRow * PT + wCol) * 4;

    float c[2][NT][4];
#pragma unroll
    for (int mt = 0; mt < 2; mt++)
#pragma unroll
        for (int nt = 0; nt < NT; nt++)
#pragma unroll
            for (int i = 0; i < 4; i++) c[mt][nt][i] = 0.0f;

    for (int k0 = 0; k0 < K; k0 += 32) {
        // ---- stage + split (once per element per block) ----
#pragma unroll
        for (int p = 0; p < 4; p++) {
            float4 av = *(const float4*)(Ap + k0 + p * 4);
            uint32_t h0, l0, h1, l1;
            split_bf16x2(av.x, av.y, h0, l0);
            split_bf16x2(av.z, av.w, h1, l1);
            sAhp[p * 2] = h0; sAhp[p * 2 + 1] = h1;
            sAlp[p * 2] = l0; sAlp[p * 2 + 1] = l1;
        }
#pragma unroll
        for (int p = 0; p < (BN == 128 ? 4 : 2); p++) {
            float4 wv = *(const float4*)(Wp + k0 + p * 4);
            uint32_t h0, l0, h1, l1;
            split_bf16x2(wv.x, wv.y, h0, l0);
            split_bf16x2(wv.z, wv.w, h1, l1);
            sWhp[p * 2] = h0; sWhp[p * 2 + 1] = h1;
            sWlp[p * 2] = l0; sWlp[p * 2 + 1] = l1;
        }
        __syncthreads();

        // ---- A fragments via ldmatrix: [mt][ks] hi+lo ----
        uint32_t ah[2][2][4], al[2][2][4];
#pragma unroll
        for (int mt = 0; mt < 2; mt++)
#pragma unroll
            for (int ks = 0; ks < 2; ks++) {
                uint32_t off = (uint32_t)((mt * 16 * PT + ks * 8) * 4);
                ldsm_x4(ah[mt][ks], aHi + off);
                ldsm_x4(al[mt][ks], aLo + off);
            }
        // ---- per n-tile: W frags (both ks in one x4) + 12 MMAs ----
#pragma unroll
        for (int nt = 0; nt < NT; nt++) {
            uint32_t bh[4], bl[4];
            uint32_t off = (uint32_t)(nt * 8 * PT * 4);
            ldsm_x4(bh, wHi + off);
            ldsm_x4(bl, wLo + off);
#pragma unroll
            for (int mt = 0; mt < 2; mt++) {
                mma16816(c[mt][nt], ah[mt][0], bh[0], bh[1]);
                mma16816(c[mt][nt], ah[mt][0], bl[0], bl[1]);
                mma16816(c[mt][nt], al[mt][0], bh[0], bh[1]);
                mma16816(c[mt][nt], ah[mt][1], bh[2], bh[3]);
                mma16816(c[mt][nt], ah[mt][1], bl[2], bl[3]);
                mma16816(c[mt][nt], al[mt][1], bh[2], bh[3]);
            }
        }
        __syncthreads();
    }

    // ---- epilogue (round-6 semantics) ----
#pragma unroll
    for (int mt = 0; mt < 2; mt++) {
#pragma unroll
        for (int half = 0; half < 2; half++) {
            int r = rowBase + m0 + mt * 16 + g + half * 8;
#pragma unroll
            for (int nt = 0; nt < NT; nt++) {
                int cc = colBase + n0 + nt * 8 + 2 * q4;
                float v0 = c[mt][nt][half * 2 + 0] + bias[cc];
                float v1 = c[mt][nt][half * 2 + 1] + bias[cc + 1];
                if (MODE == 1) { v0 = fmaxf(v0, 0.0f); v1 = fmaxf(v1, 0.0f); }
                if (MODE == 2) {
                    float2 rr = *(const float2*)&resid[(size_t)r * N + cc];
                    v0 += rr.x; v1 += rr.y;
                }
                if (MODE == 3) {
                    int s = r >> 3, b = r & 7;
                    int part = cc >> 8;
                    int h = (cc & 255) >> 5;
                    int hd = cc & 31;
                    size_t dst = ((((size_t)b * NH + h) * S_LEN + s) * HDIM) + hd;
                    if (part == 0) {
                        const float sc = 0.17677669529663687f;  // 1/sqrt(32)
                        *(float2*)&qo[dst] = make_float2(v0 * sc, v1 * sc);
                    } else if (part == 1) {
                        *(float2*)&ko[dst] = make_float2(v0, v1);
                    } else {
                        *(float2*)&vo[dst] = make_float2(v0, v1);
                    }
                } else {
                    *(float2*)&C[(size_t)r * N + cc] = make_float2(v0, v1);
                }
            }
        }
    }
}

// ================= ldmatrix bf16-split flash attention =====================
// Round-6 core; K/V fragment loads via ldmatrix.x4. P stays in registers.
// PVP=36 u32 = 144B rows: 16B-aligned; banks r*36 mod 32 distinct (conflict-free).
#define PVP 36

__global__ void __launch_bounds__(256) attn_ldsm_kernel(
    const float* __restrict__ Qg, const float* __restrict__ Kg,
    const float* __restrict__ Vg, const float* __restrict__ biasg,
    float* __restrict__ ctx)
{
    __shared__ uint32_t sKh[64 * PT], sKl[64 * PT];
    __shared__ uint32_t sVh[32 * PVP], sVl[32 * PVP];

    int tid  = threadIdx.x;
    int warp = tid >> 5, lane = tid & 31;
    int g = lane >> 2, q4 = lane & 3;
    int bh = blockIdx.y, qt = blockIdx.x;
    int b = bh >> 3, h = bh & 7;
    int rA = warp * 16 + g;
    int rB = rA + 8;

    const float* qb = Qg + ((size_t)bh * S_LEN + (size_t)qt * 128) * HDIM;
    const float* kb = Kg + (size_t)bh * S_LEN * HDIM;
    const float* vb = Vg + (size_t)bh * S_LEN * HDIM;
    const float* biasA = biasg + ((size_t)bh * S_LEN + (size_t)(qt * 128 + rA)) * S_LEN;
    const float* biasB = biasA + (size_t)8 * S_LEN;

    // ---- Q fragments (split once, held in regs) ----
    uint32_t qh[2][4], ql[2][4];
#pragma unroll
    for (int kt = 0; kt < 2; kt++) {
        int k0 = kt * 16 + 2 * q4;
        split_bf16x2(qb[rA * HDIM + k0],     qb[rA * HDIM + k0 + 1], qh[kt][0], ql[kt][0]);
        split_bf16x2(qb[rB * HDIM + k0],     qb[rB * HDIM + k0 + 1], qh[kt][1], ql[kt][1]);
        split_bf16x2(qb[rA * HDIM + k0 + 8], qb[rA * HDIM + k0 + 9], qh[kt][2], ql[kt][2]);
        split_bf16x2(qb[rB * HDIM + k0 + 8], qb[rB * HDIM + k0 + 9], qh[kt][3], ql[kt][3]);
    }

    float mA = -1e30f, mB = -1e30f, lA = 0.0f, lB = 0.0f;
    float o[4][4];
#pragma unroll
    for (int nt = 0; nt < 4; nt++)
#pragma unroll
        for (int i = 0; i < 4; i++) o[nt][i] = 0.0f;

    // staging maps
    int tK = tid >> 2, dK = (tid & 3) * 4;   // K: row t, 4 u32 (8 bf16 = 8 d)
    int uV = tid >> 3, dV = (tid & 7) * 4;   // V: t-pair uV, 4 d rows
    // ldmatrix per-lane bases
    uint32_t kHi = smem_u32(sKh) + ((uint32_t)((lane & 7) * PT + (lane >> 3) * 4)) * 4;
    uint32_t kLo = smem_u32(sKl) + ((uint32_t)((lane & 7) * PT + (lane >> 3) * 4)) * 4;
    uint32_t vHi = smem_u32(sVh) + ((uint32_t)((lane & 7) * PVP + (lane >> 3) * 4)) * 4;
    uint32_t vLo = smem_u32(sVl) + ((uint32_t)((lane & 7) * PVP + (lane >> 3) * 4)) * 4;

    for (int j = 0; j < 16; j++) {
        // ---- stage K [t][d] and V^T [d][t-pair], split once ----
        {
            const float* krow = kb + (size_t)(j * 64 + tK) * HDIM + dK * 2;
            float4 k0 = *(const float4*)(krow);
            float4 k1 = *(const float4*)(krow + 4);
            uint32_t h0, l0, h1, l1, h2, l2, h3, l3;
            split_bf16x2(k0.x, k0.y, h0, l0);
            split_bf16x2(k0.z, k0.w, h1, l1);
            split_bf16x2(k1.x, k1.y, h2, l2);
            split_bf16x2(k1.z, k1.w, h3, l3);
            uint32_t* kh = sKh + tK * PT + dK;
            uint32_t* kl = sKl + tK * PT + dK;
            kh[0] = h0; kh[1] = h1; kh[2] = h2; kh[3] = h3;
            kl[0] = l0; kl[1] = l1; kl[2] = l2; kl[3] = l3;

            const float* vr0 = vb + (size_t)(j * 64 + 2 * uV) * HDIM + dV;
            float4 v0 = *(const float4*)(vr0);
            float4 v1 = *(const float4*)(vr0 + HDIM);
            uint32_t hh, ll;
            split_bf16x2(v0.x, v1.x, hh, ll); sVh[(dV + 0) * PVP + uV] = hh; sVl[(dV + 0) * PVP + uV] = ll;
            split_bf16x2(v0.y, v1.y, hh, ll); sVh[(dV + 1) * PVP + uV] = hh; sVl[(dV + 1) * PVP + uV] = ll;
            split_bf16x2(v0.z, v1.z, hh, ll); sVh[(dV + 2) * PVP + uV] = hh; sVl[(dV + 2) * PVP + uV] = ll;
            split_bf16x2(v0.w, v1.w, hh, ll); sVh[(dV + 3) * PVP + uV] = hh; sVl[(dV + 3) * PVP + uV] = ll;
        }
        __syncthreads();

        // ---- C init with bias (read once from DRAM) ----
        float c[8][4];
#pragma unroll
        for (int nt = 0; nt < 8; nt++) {
            float2 bA = *(const float2*)(biasA + j * 64 + nt * 8 + 2 * q4);
            float2 bB = *(const float2*)(biasB + j * 64 + nt * 8 + 2 * q4);
            c[nt][0] = bA.x; c[nt][1] = bA.y; c[nt][2] = bB.x; c[nt][3] = bB.y;
        }

        // ---- QK^T: per n-tile one hi + one lo ldmatrix (both k16 steps) ----
#pragma unroll
        for (int nt = 0; nt < 8; nt++) {
            uint32_t bh4[4], bl4[4];
            uint32_t off = (uint32_t)(nt * 8 * PT * 4);
            ldsm_x4(bh4, kHi + off);
            ldsm_x4(bl4, kLo + off);
            mma16816(c[nt], qh[0], bh4[0], bh4[1]);
            mma16816(c[nt], qh[0], bl4[0], bl4[1]);
            mma16816(c[nt], ql[0], bh4[0], bh4[1]);
            mma16816(c[nt], qh[1], bh4[2], bh4[3]);
            mma16816(c[nt], qh[1], bl4[2], bl4[3]);
            mma16816(c[nt], ql[1], bh4[2], bh4[3]);
        }

        // ---- online softmax ----
        float mxA = -1e30f, mxB = -1e30f;
#pragma unroll
        for (int nt = 0; nt < 8; nt++) {
            mxA = fmaxf(mxA, fmaxf(c[nt][0], c[nt][1]));
            mxB = fmaxf(mxB, fmaxf(c[nt][2], c[nt][3]));
        }
        mxA = fmaxf(mxA, __shfl_xor_sync(0xffffffffu, mxA, 1));
        mxA = fmaxf(mxA, __shfl_xor_sync(0xffffffffu, mxA, 2));
        mxB = fmaxf(mxB, __shfl_xor_sync(0xffffffffu, mxB, 1));
        mxB = fmaxf(mxB, __shfl_xor_sync(0xffffffffu, mxB, 2));
        float nmA = fmaxf(mA, mxA), nmB = fmaxf(mB, mxB);
        float corrA = __expf(mA - nmA), corrB = __expf(mB - nmB);
        mA = nmA; mB = nmB;
        float sA2 = 0.0f, sB2 = 0.0f;
#pragma unroll
        for (int nt = 0; nt < 8; nt++) {
            c[nt][0] = __expf(c[nt][0] - nmA);
            c[nt][1] = __expf(c[nt][1] - nmA);
            c[nt][2] = __expf(c[nt][2] - nmB);
            c[nt][3] = __expf(c[nt][3] - nmB);
            sA2 += c[nt][0] + c[nt][1];
            sB2 += c[nt][2] + c[nt][3];
        }
        sA2 += __shfl_xor_sync(0xffffffffu, sA2, 1);
        sA2 += __shfl_xor_sync(0xffffffffu, sA2, 2);
        sB2 += __shfl_xor_sync(0xffffffffu, sB2, 1);
        sB2 += __shfl_xor_sync(0xffffffffu, sB2, 2);
        lA = lA * corrA + sA2;
        lB = lB * corrB + sB2;
#pragma unroll
        for (int nt = 0; nt < 4; nt++) {
            o[nt][0] *= corrA; o[nt][1] *= corrA;
            o[nt][2] *= corrB; o[nt][3] *= corrB;
        }

        // ---- repack P (C-frag == PV A-frag layout), split hi/lo ----
        uint32_t ph[4][4], pl[4][4];
#pragma unroll
        for (int kk = 0; kk < 4; kk++) {
            split_bf16x2(c[2 * kk][0],     c[2 * kk][1],     ph[kk][0], pl[kk][0]);
            split_bf16x2(c[2 * kk][2],     c[2 * kk][3],     ph[kk][1], pl[kk][1]);
            split_bf16x2(c[2 * kk + 1][0], c[2 * kk + 1][1], ph[kk][2], pl[kk][2]);
            split_bf16x2(c[2 * kk + 1][2], c[2 * kk + 1][3], ph[kk][3], pl[kk][3]);
        }

        // ---- PV: per half (t 0-31 / 32-63) per n-tile one hi + one lo x4 ----
#pragma unroll
        for (int half = 0; half < 2; half++) {
#pragma unroll
            for (int nt = 0; nt < 4; nt++) {
                uint32_t bh4[4], bl4[4];
                uint32_t off = (uint32_t)((nt * 8 * PVP + half * 16) * 4);
                ldsm_x4(bh4, vHi + off);
                ldsm_x4(bl4, vLo + off);
                mma16816(o[nt], ph[2 * half],     bh4[0], bh4[1]);
                mma16816(o[nt], ph[2 * half],     bl4[0], bl4[1]);
                mma16816(o[nt], pl[2 * half],     bh4[0], bh4[1]);
                mma16816(o[nt], ph[2 * half + 1], bh4[2], bh4[3]);
                mma16816(o[nt], ph[2 * half + 1], bl4[2], bl4[3]);
                mma16816(o[nt], pl[2 * half + 1], bh4[2], bh4[3]);
            }
        }
        __syncthreads();
    }

    // ---- epilogue: normalize, write ctx[S,B,D] ----
    float invA = 1.0f / lA, invB = 1.0f / lB;
    float* cA = ctx + ((size_t)(qt * 128 + rA) * BATCH + b) * DMODEL + h * HDIM;
    float* cB = ctx + ((size_t)(qt * 128 + rB) * BATCH + b) * DMODEL + h * HDIM;
#pragma unroll
    for (int nt = 0; nt < 4; nt++) {
        *(float2*)(cA + nt * 8 + 2 * q4) = make_float2(o[nt][0] * invA, o[nt][1] * invA);
        *(float2*)(cB + nt * 8 + 2 * q4) = make_float2(o[nt][2] * invB, o[nt][3] * invB);
    }
}

// ---------------- launch ---------------------------------------------------
extern "C" void kernel_launch(void* const* d_in, const int* in_sizes, int n_in,
                              void* d_out, int out_size) {
    const float* src   = (const float*)d_in[0];
    const float* bias  = (const float*)d_in[1];
    const float* in_w  = (const float*)d_in[2];
    const float* in_b  = (const float*)d_in[3];
    const float* out_w = (const float*)d_in[4];
    const float* out_b = (const float*)d_in[5];
    const float* w1    = (const float*)d_in[6];
    const float* b1    = (const float*)d_in[7];
    const float* w2    = (const float*)d_in[8];
    const float* b2    = (const float*)d_in[9];
    const float* g1    = (const float*)d_in[10];
    const float* be1   = (const float*)d_in[11];
    const float* g2    = (const float*)d_in[12];
    const float* be2   = (const float*)d_in[13];
    float* out = (float*)d_out;

    float *px, *pq, *pk, *pv, *pctx, *px2, *py, *pff1;
    cudaGetSymbolAddress((void**)&px,   g_x);
    cudaGetSymbolAddress((void**)&pq,   g_q);
    cudaGetSymbolAddress((void**)&pk,   g_k);
    cudaGetSymbolAddress((void**)&pv,   g_v);
    cudaGetSymbolAddress((void**)&pctx, g_ctx);
    cudaGetSymbolAddress((void**)&px2,  g_x2);
    cudaGetSymbolAddress((void**)&py,   g_y);
    cudaGetSymbolAddress((void**)&pff1, g_ff1);

    dim3 lnb(32, 8);
    // 1. x = LN1(src)
    ln_kernel<<<MROWS / 8, lnb>>>(src, g1, be1, px);
    // 2. qkv = x @ in_w^T + in_b -> scattered q/k/v head layout
    gemm_ldsm_kernel<3, 128><<<dim3(6, 64), 256>>>(
        px, in_w, in_b, nullptr, nullptr, pq, pk, pv, DMODEL, 3 * DMODEL);
    // 3. flash attention with bias -> ctx [S,B,D]
    attn_ldsm_kernel<<<dim3(8, 64), 256>>>(pq, pk, pv, bias, pctx);
    // 4. x2 = x + ctx @ out_w^T + out_b
    gemm_ldsm_kernel<2, 64><<<dim3(4, 64), 256>>>(
        pctx, out_w, out_b, px, px2, nullptr, nullptr, nullptr, DMODEL, DMODEL);
    // 5. y = LN2(x2)
    ln_kernel<<<MROWS / 8, lnb>>>(px2, g2, be2, py);
    // 6. ff1 = relu(y @ w1^T + b1)
    gemm_ldsm_kernel<1, 128><<<dim3(8, 64), 256>>>(
        py, w1, b1, nullptr, pff1, nullptr, nullptr, nullptr, DMODEL, DFF);
    // 7. out = y + ff1 @ w2^T + b2
    gemm_ldsm_kernel<2, 64><<<dim3(4, 64), 256>>>(
        pff1, w2, b2, py, out, nullptr, nullptr, nullptr, DFF, DMODEL);
}